// round 2
// baseline (speedup 1.0000x reference)
#include <cuda_runtime.h>
#include <math.h>

#define MODS 2
#define BB 32
#define CC 1000
#define HH 512
#define NNODE 1001
#define NP 1024
#define TILE 128
#define TTILES (NP / TILE)                  /* 8  */
#define NPAIRS (TTILES * (TTILES + 1) / 2)  /* 36 */
#define ALPHA_IT 0.7f
#define BETA_IT 0.5f

// ---------------- scratch (device globals; no runtime allocation) ----------
__device__ float g_xn[MODS][BB][NP][HH];   // normalized features, node-major (134 MB)
__device__ float g_s[MODS][BB][NP];        // rowsums of relu(gram)
__device__ float g_cos0[MODS][BB][NP];     // gram row 0
__device__ float g_w[MODS][BB][NP];        // adjacency row-0 weights
__device__ float g_v[MODS][BB][HH];        // weighted feature sum
__device__ float g_t[MODS][BB][HH];        // tanh(v @ W + bias0)

// upper-triangular tile-pair LUT for 8x8 tiles (36 pairs)
__device__ __constant__ unsigned char c_ti[NPAIRS] = {
    0,0,0,0,0,0,0,0, 1,1,1,1,1,1,1, 2,2,2,2,2,2, 3,3,3,3,3, 4,4,4,4, 5,5,5, 6,6, 7};
__device__ __constant__ unsigned char c_tj[NPAIRS] = {
    0,1,2,3,4,5,6,7, 1,2,3,4,5,6,7, 2,3,4,5,6,7, 3,4,5,6,7, 4,5,6,7, 5,6,7, 6,7, 7};

// ---------------- 1) normalize features into node-major layout ------------
// block = one (mod, b, node); 128 threads; also zeroes g_s.
__global__ void k_norm(const float* __restrict__ in_txt,
                       const float* __restrict__ base_txt,
                       const float* __restrict__ in_img,
                       const float* __restrict__ base_img) {
    int idx = blockIdx.x;
    int n   = idx & (NP - 1);
    int b   = (idx >> 10) & 31;
    int mod = idx >> 15;
    int t   = threadIdx.x;  // 0..127

    float vals[4];
    float ss = 0.f;
    if (n < NNODE) {
        const float* inp = mod ? in_img : in_txt;
        const float* bas = mod ? base_img : base_txt;
        const float* src = (n == 0) ? (inp + (size_t)b * HH)
                                    : (bas + ((size_t)b * CC + (n - 1)) * HH);
#pragma unroll
        for (int i = 0; i < 4; i++) {
            vals[i] = src[t + i * 128];
            ss += vals[i] * vals[i];
        }
    }
    __shared__ float red[4];
#pragma unroll
    for (int o = 16; o; o >>= 1) ss += __shfl_down_sync(0xffffffffu, ss, o);
    if ((t & 31) == 0) red[t >> 5] = ss;
    __syncthreads();
    if (t == 0) {
        float tot = red[0] + red[1] + red[2] + red[3];
        float nrm = fmaxf(sqrtf(tot), 1e-12f);
        red[0] = 1.0f / nrm;
        g_s[mod][b][n] = 0.f;
    }
    __syncthreads();
    float inv = red[0];
    float* dst = &g_xn[mod][b][n][0];
    if (n < NNODE) {
#pragma unroll
        for (int i = 0; i < 4; i++) dst[t + i * 128] = vals[i] * inv;
    } else {
#pragma unroll
        for (int i = 0; i < 4; i++) dst[t + i * 128] = 0.f;
    }
}

// ---------------- 2) symmetric gram + relu row-sums -----------------------
// One block per upper-triangular 128x128 tile pair per (mod, b).
// 256 threads, 8x8 register micro-tile, K-chunks of 8.
__global__ __launch_bounds__(256) void k_gram() {
    int mod = blockIdx.z, b = blockIdx.y, p = blockIdx.x;
    int ti = c_ti[p], tj = c_tj[p];

    const float* Ag = &g_xn[mod][b][ti * TILE][0];
    const float* Bg = &g_xn[mod][b][tj * TILE][0];

    __shared__ float As[8][132];
    __shared__ float Bs[8][132];
    __shared__ float red[TILE][17];

    int tid  = threadIdx.x;
    int tx   = tid & 15, ty = tid >> 4;
    int lrow = tid >> 1, lseg = tid & 1;

    float acc[8][8];
#pragma unroll
    for (int i = 0; i < 8; i++)
#pragma unroll
        for (int j = 0; j < 8; j++) acc[i][j] = 0.f;

    for (int k0 = 0; k0 < HH; k0 += 8) {
        float4 a4 = *(const float4*)(Ag + (size_t)lrow * HH + k0 + lseg * 4);
        float4 b4 = *(const float4*)(Bg + (size_t)lrow * HH + k0 + lseg * 4);
        __syncthreads();  // previous compute done before overwrite
        As[lseg * 4 + 0][lrow] = a4.x;
        As[lseg * 4 + 1][lrow] = a4.y;
        As[lseg * 4 + 2][lrow] = a4.z;
        As[lseg * 4 + 3][lrow] = a4.w;
        Bs[lseg * 4 + 0][lrow] = b4.x;
        Bs[lseg * 4 + 1][lrow] = b4.y;
        Bs[lseg * 4 + 2][lrow] = b4.z;
        Bs[lseg * 4 + 3][lrow] = b4.w;
        __syncthreads();
#pragma unroll
        for (int kk = 0; kk < 8; kk++) {
            float ar[8], br[8];
#pragma unroll
            for (int i = 0; i < 8; i++) ar[i] = As[kk][ty * 8 + i];
#pragma unroll
            for (int j = 0; j < 8; j++) br[j] = Bs[kk][tx * 8 + j];
#pragma unroll
            for (int i = 0; i < 8; i++)
#pragma unroll
                for (int j = 0; j < 8; j++)
                    acc[i][j] = fmaf(ar[i], br[j], acc[i][j]);
        }
    }

    // relu + partial sums (rows for tile i, cols for tile j via symmetry)
    float pr[8], pc[8];
#pragma unroll
    for (int i = 0; i < 8; i++) { pr[i] = 0.f; pc[i] = 0.f; }
#pragma unroll
    for (int i = 0; i < 8; i++)
#pragma unroll
        for (int j = 0; j < 8; j++) {
            float v = fmaxf(acc[i][j], 0.f);
            pr[i] += v;
            pc[j] += v;
        }

#pragma unroll
    for (int i = 0; i < 8; i++) red[ty * 8 + i][tx] = pr[i];
    __syncthreads();
    if (tid < TILE) {
        float s = 0.f;
#pragma unroll
        for (int q = 0; q < 16; q++) s += red[tid][q];
        atomicAdd(&g_s[mod][b][ti * TILE + tid], s);
    }
    if (ti != tj) {
        __syncthreads();
#pragma unroll
        for (int j = 0; j < 8; j++) red[tx * 8 + j][ty] = pc[j];
        __syncthreads();
        if (tid < TILE) {
            float s = 0.f;
#pragma unroll
            for (int q = 0; q < 16; q++) s += red[tid][q];
            atomicAdd(&g_s[mod][b][tj * TILE + tid], s);
        }
    }
}

// ---------------- 3) gram row 0 (cos0) ------------------------------------
__global__ void k_cos0() {
    int gw   = (int)((blockIdx.x * blockDim.x + threadIdx.x) >> 5);
    int lane = threadIdx.x & 31;
    int m = gw & (NP - 1);
    int b = (gw >> 10) & 31;
    int mod = gw >> 15;
    const float* x0 = &g_xn[mod][b][0][0];
    const float* xm = &g_xn[mod][b][m][0];
    float s = 0.f;
#pragma unroll
    for (int i = 0; i < 16; i++) s += x0[lane + i * 32] * xm[lane + i * 32];
#pragma unroll
    for (int o = 16; o; o >>= 1) s += __shfl_down_sync(0xffffffffu, s, o);
    if (lane == 0) g_cos0[mod][b][m] = s;
}

// ---------------- 4) adjacency row-0 weights; zero g_v --------------------
__global__ void k_w() {
    int idx = blockIdx.x * blockDim.x + threadIdx.x;  // < 65536
    int m = idx & (NP - 1);
    int b = (idx >> 10) & 31;
    int mod = idx >> 15;
    float s0 = g_s[mod][b][0] + 1.f;
    float sm = g_s[mod][b][m] + 1.f;
    float a  = fmaxf(g_cos0[mod][b][m], 0.f) + (m == 0 ? 1.f : 0.f);
    g_w[mod][b][m] = rsqrtf(s0) * a * rsqrtf(sm);
    if (idx < MODS * BB * HH) ((float*)g_v)[idx] = 0.f;
}

// ---------------- 5) weighted raw-feature sum: v[b,h] ---------------------
// grid = (mod, b, c-chunk of 250); 512 threads (one per h); atomic accumulate.
__global__ void k_v(const float* __restrict__ in_txt,
                    const float* __restrict__ base_txt,
                    const float* __restrict__ in_img,
                    const float* __restrict__ base_img) {
    int blk = blockIdx.x;
    int cc  = blk & 3;
    int b   = (blk >> 2) & 31;
    int mod = blk >> 7;
    int h   = threadIdx.x;
    const float* inp = mod ? in_img : in_txt;
    const float* bas = mod ? base_img : base_txt;
    const float* wv  = g_w[mod][b];
    float acc = 0.f;
    if (cc == 0) acc = wv[0] * inp[(size_t)b * HH + h];
    const float* bp = bas + ((size_t)b * CC + cc * 250) * HH + h;
    const float* wp = wv + 1 + cc * 250;
#pragma unroll 10
    for (int c = 0; c < 250; c++) acc += wp[c] * bp[(size_t)c * HH];
    atomicAdd(&g_v[mod][b][h], acc);
}

// ---------------- 6) tiny GEMM + tanh: g_t = tanh(v @ W + bias0) ----------
__global__ void k_g(const float* __restrict__ W_tt, const float* __restrict__ b_tt,
                    const float* __restrict__ W_it, const float* __restrict__ b_it) {
    int mod = blockIdx.x >> 5;
    int b   = blockIdx.x & 31;
    const float* W  = mod ? W_it : W_tt;
    const float* bb = mod ? b_it : b_tt;  // row 0 of [N, H]
    __shared__ float vs[HH];
    int k = threadIdx.x;
    vs[k] = g_v[mod][b][k];
    __syncthreads();
    float acc = bb[k];
#pragma unroll 8
    for (int hh = 0; hh < HH; hh++) acc += vs[hh] * W[(size_t)hh * HH + k];
    g_t[mod][b][k] = tanhf(acc);
}

// ---------------- 7) final blend ------------------------------------------
__global__ void k_out(const float* __restrict__ base_txt,
                      const float* __restrict__ base_img,
                      float* __restrict__ out) {
    size_t i4 = (size_t)blockIdx.x * blockDim.x + threadIdx.x;
    const size_t half4 = (size_t)BB * CC * HH / 4;  // 4,096,000
    if (i4 >= 2 * half4) return;
    int mod  = i4 >= half4;
    size_t j = mod ? i4 - half4 : i4;
    size_t e = j * 4;
    int b = (int)(e / ((size_t)CC * HH));
    int h = (int)(e & (HH - 1));
    const float* base = mod ? base_img : base_txt;
    float4 bv = *(const float4*)(base + e);
    float4 t0 = *(const float4*)(&g_t[0][b][h]);
    float4 t1 = *(const float4*)(&g_t[1][b][h]);
    float4 o;
    o.x = BETA_IT * bv.x + (1.f - BETA_IT) * (ALPHA_IT * t0.x + (1.f - ALPHA_IT) * t1.x);
    o.y = BETA_IT * bv.y + (1.f - BETA_IT) * (ALPHA_IT * t0.y + (1.f - ALPHA_IT) * t1.y);
    o.z = BETA_IT * bv.z + (1.f - BETA_IT) * (ALPHA_IT * t0.z + (1.f - ALPHA_IT) * t1.z);
    o.w = BETA_IT * bv.w + (1.f - BETA_IT) * (ALPHA_IT * t0.w + (1.f - ALPHA_IT) * t1.w);
    *(float4*)(out + i4 * 4) = o;
}

// ---------------- launch ---------------------------------------------------
extern "C" void kernel_launch(void* const* d_in, const int* in_sizes, int n_in,
                              void* d_out, int out_size) {
    const float* in_txt  = (const float*)d_in[0];
    const float* in_img  = (const float*)d_in[1];
    const float* base_t  = (const float*)d_in[2];
    const float* base_i  = (const float*)d_in[3];
    const float* W_tt    = (const float*)d_in[4];
    const float* bias_tt = (const float*)d_in[5];
    const float* W_it    = (const float*)d_in[6];
    const float* bias_it = (const float*)d_in[7];
    float* out = (float*)d_out;

    k_norm<<<MODS * BB * NP, 128>>>(in_txt, base_t, in_img, base_i);
    k_gram<<<dim3(NPAIRS, BB, MODS), 256>>>();
    k_cos0<<<MODS * BB * NP / 8, 256>>>();
    k_w<<<MODS * BB * NP / 256, 256>>>();
    k_v<<<MODS * BB * 4, 512>>>(in_txt, base_t, in_img, base_i);
    k_g<<<MODS * BB, 512>>>(W_tt, bias_tt, W_it, bias_it);
    k_out<<<(int)((2u * BB * CC * HH / 4 + 255) / 256), 256>>>(base_t, base_i, out);
}

// round 5
// speedup vs baseline: 1.9256x; 1.9256x over previous
#include <cuda_runtime.h>
#include <cuda_bf16.h>
#include <math.h>
#include <stdint.h>

#define MODS 2
#define BB 32
#define CC 1000
#define HH 512
#define NNODE 1001
#define NP 1024
#define TILE 128
#define TTILES (NP / TILE)                  /* 8  */
#define NPAIRS (TTILES * (TTILES + 1) / 2)  /* 36 */
#define ALPHA_IT 0.7f
#define BETA_IT 0.5f

// ---------------- scratch --------------------------------------------------
__device__ __nv_bfloat16 g_hi[MODS][BB][NP][HH];  // 67 MB
__device__ __nv_bfloat16 g_lo[MODS][BB][NP][HH];  // 67 MB
__device__ float g_s[MODS][BB][NP];
__device__ float g_cos0[MODS][BB][NP];            // relu'd gram row 0
__device__ float g_w[MODS][BB][NP];
__device__ float g_v[MODS][BB][HH];
__device__ float g_t[MODS][BB][HH];

__device__ __constant__ unsigned char c_ti[NPAIRS] = {
    0,0,0,0,0,0,0,0, 1,1,1,1,1,1,1, 2,2,2,2,2,2, 3,3,3,3,3, 4,4,4,4, 5,5,5, 6,6, 7};
__device__ __constant__ unsigned char c_tj[NPAIRS] = {
    0,1,2,3,4,5,6,7, 1,2,3,4,5,6,7, 2,3,4,5,6,7, 3,4,5,6,7, 4,5,6,7, 5,6,7, 6,7, 7};

__device__ __forceinline__ uint32_t smem_u32(const void* p) {
    uint32_t a;
    asm("{ .reg .u64 t; cvta.to.shared.u64 t, %1; cvt.u32.u64 %0, t; }" : "=r"(a) : "l"(p));
    return a;
}

// ---------------- 1) normalize + bf16 hi/lo split; zero g_s ----------------
__global__ void k_norm(const float* __restrict__ in_txt,
                       const float* __restrict__ base_txt,
                       const float* __restrict__ in_img,
                       const float* __restrict__ base_img) {
    int idx = blockIdx.x;
    int n   = idx & (NP - 1);
    int b   = (idx >> 10) & 31;
    int mod = idx >> 15;
    int t   = threadIdx.x;  // 0..127

    float vals[4];
    float ss = 0.f;
    if (n < NNODE) {
        const float* inp = mod ? in_img : in_txt;
        const float* bas = mod ? base_img : base_txt;
        const float* src = (n == 0) ? (inp + (size_t)b * HH)
                                    : (bas + ((size_t)b * CC + (n - 1)) * HH);
#pragma unroll
        for (int i = 0; i < 4; i++) {
            vals[i] = src[t + i * 128];
            ss += vals[i] * vals[i];
        }
    } else {
#pragma unroll
        for (int i = 0; i < 4; i++) vals[i] = 0.f;
    }
    __shared__ float red[4];
#pragma unroll
    for (int o = 16; o; o >>= 1) ss += __shfl_down_sync(0xffffffffu, ss, o);
    if ((t & 31) == 0) red[t >> 5] = ss;
    __syncthreads();
    if (t == 0) {
        float tot = red[0] + red[1] + red[2] + red[3];
        red[0] = 1.0f / fmaxf(sqrtf(tot), 1e-12f);
        g_s[mod][b][n] = 0.f;
    }
    __syncthreads();
    float inv = (n < NNODE) ? red[0] : 0.f;
#pragma unroll
    for (int i = 0; i < 4; i++) {
        float x = vals[i] * inv;
        __nv_bfloat16 h = __float2bfloat16(x);
        __nv_bfloat16 l = __float2bfloat16(x - __bfloat162float(h));
        g_hi[mod][b][n][t + i * 128] = h;
        g_lo[mod][b][n][t + i * 128] = l;
    }
}

// ---------------- 2) mma.sync symmetric gram + relu row/col sums -----------
// Split-bf16 as one virtual GEMM over K'=1536:
//   A' = [Ahi | Ahi | Alo],  B' = [Bhi | Blo | Bhi],  C = A'.B'^T (fp32 accum)
// BM=BN=128, BK=32, 256 threads, warp tile 64x32, cp.async double buffering.
#define BK 32
#define LDS 40                       /* padded smem row stride in bf16 */
#define CHUNK_B (TILE * LDS * 2)     /* 10240 bytes per matrix buffer  */
#define NCHUNK 48                    /* 1536 / 32 */

__global__ __launch_bounds__(256, 2) void k_gram_mma() {
    __shared__ __align__(16) char smem[4 * CHUNK_B];  // A[2] then B[2]

    int mod = blockIdx.z, b = blockIdx.y, p = blockIdx.x;
    int ti = c_ti[p], tj = c_tj[p];
    int tid  = threadIdx.x;
    int w    = tid >> 5, lane = tid & 31;
    int wm   = w >> 2, wn = w & 3;           // warp grid 2x4
    int g    = lane >> 2, tig = lane & 3;

    const __nv_bfloat16* Ahi = &g_hi[mod][b][ti * TILE][0];
    const __nv_bfloat16* Alo = &g_lo[mod][b][ti * TILE][0];
    const __nv_bfloat16* Bhi = &g_hi[mod][b][tj * TILE][0];
    const __nv_bfloat16* Blo = &g_lo[mod][b][tj * TILE][0];

    float acc[4][4][4];
#pragma unroll
    for (int i = 0; i < 4; i++)
#pragma unroll
        for (int j = 0; j < 4; j++)
#pragma unroll
            for (int q = 0; q < 4; q++) acc[i][j][q] = 0.f;

    uint32_t sA0 = smem_u32(smem);
    uint32_t sB0 = sA0 + 2 * CHUNK_B;

    // per-thread load slots: slot s = tid; row = s>>2, seg = s&3
    int lr0 = tid >> 2, lseg = tid & 3;

    // issue cp.async loads of chunk c into buffer buf
    auto issue = [&](int c, int buf) {
        int prod = c >> 4;             // 0,1,2
        int k0   = (c & 15) * BK;
        const __nv_bfloat16* As = (prod < 2) ? Ahi : Alo;
        const __nv_bfloat16* Bs = (prod == 1) ? Blo : Bhi;
        uint32_t da = sA0 + buf * CHUNK_B;
        uint32_t db = sB0 + buf * CHUNK_B;
#pragma unroll
        for (int i = 0; i < 2; i++) {
            int r = lr0 + i * 64;
            uint32_t off = (uint32_t)(r * LDS + lseg * 8) * 2;
            const void* ga = (const char*)(As + (size_t)r * HH + k0 + lseg * 8);
            const void* gb = (const char*)(Bs + (size_t)r * HH + k0 + lseg * 8);
            asm volatile("cp.async.cg.shared.global [%0], [%1], 16;" :: "r"(da + off), "l"(ga));
            asm volatile("cp.async.cg.shared.global [%0], [%1], 16;" :: "r"(db + off), "l"(gb));
        }
        asm volatile("cp.async.commit_group;" ::: "memory");
    };

    // ldmatrix lane addresses (byte offsets within a buffer)
    uint32_t a_lrow = (uint32_t)(wm * 64 + (lane & 15));
    uint32_t a_lcol = (uint32_t)((lane >> 4) * 8);
    uint32_t b_lrow = (uint32_t)(wn * 32 + (lane & 7) + (lane >> 4) * 8);
    uint32_t b_lcol = (uint32_t)(((lane >> 3) & 1) * 8);

    issue(0, 0);
    for (int c = 0; c < NCHUNK; c++) {
        int buf = c & 1;
        if (c + 1 < NCHUNK) issue(c + 1, buf ^ 1);
        if (c + 1 < NCHUNK)
            asm volatile("cp.async.wait_group 1;" ::: "memory");
        else
            asm volatile("cp.async.wait_group 0;" ::: "memory");
        __syncthreads();

        uint32_t da = sA0 + buf * CHUNK_B;
        uint32_t db = sB0 + buf * CHUNK_B;
#pragma unroll
        for (int kk = 0; kk < 2; kk++) {
            uint32_t afr[4][4];
            uint32_t bfr[4][2];
            uint32_t aaddr = da + ((a_lrow * LDS) + kk * 16 + a_lcol) * 2;
#pragma unroll
            for (int mi = 0; mi < 4; mi++) {
                asm volatile("ldmatrix.sync.aligned.m8n8.x4.shared.b16 {%0,%1,%2,%3}, [%4];"
                             : "=r"(afr[mi][0]), "=r"(afr[mi][1]),
                               "=r"(afr[mi][2]), "=r"(afr[mi][3])
                             : "r"(aaddr + (uint32_t)(mi * 16 * LDS * 2)));
            }
            uint32_t baddr = db + ((b_lrow * LDS) + kk * 16 + b_lcol) * 2;
#pragma unroll
            for (int nj = 0; nj < 2; nj++) {
                asm volatile("ldmatrix.sync.aligned.m8n8.x4.shared.b16 {%0,%1,%2,%3}, [%4];"
                             : "=r"(bfr[nj * 2][0]), "=r"(bfr[nj * 2][1]),
                               "=r"(bfr[nj * 2 + 1][0]), "=r"(bfr[nj * 2 + 1][1])
                             : "r"(baddr + (uint32_t)(nj * 16 * LDS * 2)));
            }
#pragma unroll
            for (int mi = 0; mi < 4; mi++)
#pragma unroll
                for (int ni = 0; ni < 4; ni++) {
                    asm volatile(
                        "mma.sync.aligned.m16n8k16.row.col.f32.bf16.bf16.f32 "
                        "{%0,%1,%2,%3}, {%4,%5,%6,%7}, {%8,%9}, {%0,%1,%2,%3};"
                        : "+f"(acc[mi][ni][0]), "+f"(acc[mi][ni][1]),
                          "+f"(acc[mi][ni][2]), "+f"(acc[mi][ni][3])
                        : "r"(afr[mi][0]), "r"(afr[mi][1]),
                          "r"(afr[mi][2]), "r"(afr[mi][3]),
                          "r"(bfr[ni][0]), "r"(bfr[ni][1]));
                }
        }
        __syncthreads();
    }

    // ---------------- epilogue: relu + row/col sums + cos0 -----------------
    float* srow = (float*)smem;        // [128]
    float* scol = srow + TILE;         // [128]
    if (tid < TILE) { srow[tid] = 0.f; scol[tid] = 0.f; }
    __syncthreads();

#pragma unroll
    for (int mi = 0; mi < 4; mi++)
#pragma unroll
        for (int ni = 0; ni < 4; ni++)
#pragma unroll
            for (int q = 0; q < 4; q++)
                acc[mi][ni][q] = fmaxf(acc[mi][ni][q], 0.f);

    // row sums: thread covers rows wm*64+mi*16+h*8+g
#pragma unroll
    for (int mi = 0; mi < 4; mi++)
#pragma unroll
        for (int h = 0; h < 2; h++) {
            float rv = 0.f;
#pragma unroll
            for (int ni = 0; ni < 4; ni++)
                rv += acc[mi][ni][2 * h] + acc[mi][ni][2 * h + 1];
            rv += __shfl_xor_sync(0xffffffffu, rv, 1);
            rv += __shfl_xor_sync(0xffffffffu, rv, 2);
            if (tig == 0) atomicAdd(&srow[wm * 64 + mi * 16 + h * 8 + g], rv);
        }
    // col sums: thread covers cols wn*32+ni*8+tig*2+par
#pragma unroll
    for (int ni = 0; ni < 4; ni++)
#pragma unroll
        for (int par = 0; par < 2; par++) {
            float cv = 0.f;
#pragma unroll
            for (int mi = 0; mi < 4; mi++)
                cv += acc[mi][ni][par] + acc[mi][ni][2 + par];
            cv += __shfl_xor_sync(0xffffffffu, cv, 4);
            cv += __shfl_xor_sync(0xffffffffu, cv, 8);
            cv += __shfl_xor_sync(0xffffffffu, cv, 16);
            if (g == 0) atomicAdd(&scol[wn * 32 + ni * 8 + tig * 2 + par], cv);
        }
    // cos0: global row 0 lives in warps wm==0, mi==0, h==0, lanes g==0
    if (ti == 0 && wm == 0 && g == 0) {
#pragma unroll
        for (int ni = 0; ni < 4; ni++)
#pragma unroll
            for (int par = 0; par < 2; par++)
                g_cos0[mod][b][tj * TILE + wn * 32 + ni * 8 + tig * 2 + par] =
                    acc[0][ni][par];
    }
    __syncthreads();
    if (tid < TILE) {
        atomicAdd(&g_s[mod][b][ti * TILE + tid], srow[tid]);
        if (ti != tj) atomicAdd(&g_s[mod][b][tj * TILE + tid], scol[tid]);
    }
}

// ---------------- 3) adjacency row-0 weights; zero g_v --------------------
__global__ void k_w() {
    int idx = blockIdx.x * blockDim.x + threadIdx.x;  // < 65536
    int m = idx & (NP - 1);
    int b = (idx >> 10) & 31;
    int mod = idx >> 15;
    float s0 = g_s[mod][b][0] + 1.f;
    float sm = g_s[mod][b][m] + 1.f;
    float a  = fmaxf(g_cos0[mod][b][m], 0.f) + (m == 0 ? 1.f : 0.f);
    g_w[mod][b][m] = rsqrtf(s0) * a * rsqrtf(sm);
    if (idx < MODS * BB * HH) ((float*)g_v)[idx] = 0.f;
}

// ---------------- 4) weighted raw-feature sum: v[b,h] ---------------------
__global__ void k_v(const float* __restrict__ in_txt,
                    const float* __restrict__ base_txt,
                    const float* __restrict__ in_img,
                    const float* __restrict__ base_img) {
    int blk = blockIdx.x;
    int cc  = blk & 3;
    int b   = (blk >> 2) & 31;
    int mod = blk >> 7;
    int h   = threadIdx.x;
    const float* inp = mod ? in_img : in_txt;
    const float* bas = mod ? base_img : base_txt;
    const float* wv  = g_w[mod][b];
    float acc = 0.f;
    if (cc == 0) acc = wv[0] * inp[(size_t)b * HH + h];
    const float* bp = bas + ((size_t)b * CC + cc * 250) * HH + h;
    const float* wp = wv + 1 + cc * 250;
#pragma unroll 10
    for (int c = 0; c < 250; c++) acc += wp[c] * bp[(size_t)c * HH];
    atomicAdd(&g_v[mod][b][h], acc);
}

// ---------------- 5) tiny GEMM + tanh -------------------------------------
__global__ void k_g(const float* __restrict__ W_tt, const float* __restrict__ b_tt,
                    const float* __restrict__ W_it, const float* __restrict__ b_it) {
    int mod = blockIdx.x >> 5;
    int b   = blockIdx.x & 31;
    const float* W  = mod ? W_it : W_tt;
    const float* bb = mod ? b_it : b_tt;
    __shared__ float vs[HH];
    int k = threadIdx.x;
    vs[k] = g_v[mod][b][k];
    __syncthreads();
    float acc = bb[k];
#pragma unroll 8
    for (int hh = 0; hh < HH; hh++) acc += vs[hh] * W[(size_t)hh * HH + k];
    g_t[mod][b][k] = tanhf(acc);
}

// ---------------- 6) final blend ------------------------------------------
__global__ void k_out(const float* __restrict__ base_txt,
                      const float* __restrict__ base_img,
                      float* __restrict__ out) {
    size_t i4 = (size_t)blockIdx.x * blockDim.x + threadIdx.x;
    const size_t half4 = (size_t)BB * CC * HH / 4;
    if (i4 >= 2 * half4) return;
    int mod  = i4 >= half4;
    size_t j = mod ? i4 - half4 : i4;
    size_t e = j * 4;
    int b = (int)(e / ((size_t)CC * HH));
    int h = (int)(e & (HH - 1));
    const float* base = mod ? base_img : base_txt;
    float4 bv = *(const float4*)(base + e);
    float4 t0 = *(const float4*)(&g_t[0][b][h]);
    float4 t1 = *(const float4*)(&g_t[1][b][h]);
    float4 o;
    o.x = BETA_IT * bv.x + (1.f - BETA_IT) * (ALPHA_IT * t0.x + (1.f - ALPHA_IT) * t1.x);
    o.y = BETA_IT * bv.y + (1.f - BETA_IT) * (ALPHA_IT * t0.y + (1.f - ALPHA_IT) * t1.y);
    o.z = BETA_IT * bv.z + (1.f - BETA_IT) * (ALPHA_IT * t0.z + (1.f - ALPHA_IT) * t1.z);
    o.w = BETA_IT * bv.w + (1.f - BETA_IT) * (ALPHA_IT * t0.w + (1.f - ALPHA_IT) * t1.w);
    *(float4*)(out + i4 * 4) = o;
}

// ---------------- launch ---------------------------------------------------
extern "C" void kernel_launch(void* const* d_in, const int* in_sizes, int n_in,
                              void* d_out, int out_size) {
    const float* in_txt  = (const float*)d_in[0];
    const float* in_img  = (const float*)d_in[1];
    const float* base_t  = (const float*)d_in[2];
    const float* base_i  = (const float*)d_in[3];
    const float* W_tt    = (const float*)d_in[4];
    const float* bias_tt = (const float*)d_in[5];
    const float* W_it    = (const float*)d_in[6];
    const float* bias_it = (const float*)d_in[7];
    float* out = (float*)d_out;

    k_norm<<<MODS * BB * NP, 128>>>(in_txt, base_t, in_img, base_i);
    k_gram_mma<<<dim3(NPAIRS, BB, MODS), 256>>>();
    k_w<<<MODS * BB * NP / 256, 256>>>();
    k_v<<<MODS * BB * 4, 512>>>(in_txt, base_t, in_img, base_i);
    k_g<<<MODS * BB, 512>>>(W_tt, bias_tt, W_it, bias_it);
    k_out<<<(int)((2u * BB * CC * HH / 4 + 255) / 256), 256>>>(base_t, base_i, out);
}